// round 2
// baseline (speedup 1.0000x reference)
#include <cuda_runtime.h>
#include <cuda_bf16.h>
#include <math.h>

// ---------------- problem constants ----------------
#define BB 4
#define SS 2048
#define DD 1024
#define HH 16
#define HSZ 64
#define DFF 4096
#define NROWS (BB * SS)          // 8192
#define QKV_N (3 * DD)           // 3072

// ---------------- scratch (static device globals; no cudaMalloc allowed) ----
__device__ float g_h[NROWS * DD];        // LN output (reused for ln1 and ln2)
__device__ float g_qkv[NROWS * QKV_N];   // Q|K|V, head-concat per row
__device__ float g_wqkv[DD * QKV_N];     // packed qkv weights [d][n]
__device__ float g_o[NROWS * DD];        // attention output (head-concat)
__device__ float g_ffh[NROWS * DFF];     // FFN hidden

// ==================== weight repack: wq/wk/wv [H,D,HS] -> W[d][n] ===========
__global__ void repack_kernel(const float* __restrict__ wq,
                              const float* __restrict__ wk,
                              const float* __restrict__ wv,
                              float* __restrict__ W)
{
    int idx = blockIdx.x * 256 + threadIdx.x;
    if (idx >= DD * QKV_N) return;
    int d = idx / QKV_N;
    int n = idx % QKV_N;
    int sel = n >> 10;          // 0:q 1:k 2:v
    int nn  = n & 1023;
    int hh  = nn >> 6;
    int e   = nn & 63;
    const float* src = (sel == 0) ? wq : (sel == 1) ? wk : wv;
    W[idx] = src[((size_t)hh * DD + d) * HSZ + e];
}

// ==================== LayerNorm: one block per row (1024 cols) ==============
__global__ void ln_kernel(const float* __restrict__ in,
                          const float* __restrict__ gg,
                          const float* __restrict__ bb,
                          float* __restrict__ out)
{
    int row = blockIdx.x;
    const float* x = in + (size_t)row * DD;
    float v[4];
    float s = 0.f, s2 = 0.f;
#pragma unroll
    for (int k = 0; k < 4; k++) {
        v[k] = x[threadIdx.x + k * 256];
        s  += v[k];
        s2 += v[k] * v[k];
    }
#pragma unroll
    for (int off = 16; off; off >>= 1) {
        s  += __shfl_xor_sync(0xffffffffu, s,  off);
        s2 += __shfl_xor_sync(0xffffffffu, s2, off);
    }
    __shared__ float red[2][8];
    int wid = threadIdx.x >> 5, lane = threadIdx.x & 31;
    if (lane == 0) { red[0][wid] = s; red[1][wid] = s2; }
    __syncthreads();
    float S = 0.f, S2 = 0.f;
#pragma unroll
    for (int w = 0; w < 8; w++) { S += red[0][w]; S2 += red[1][w]; }
    float mean = S * (1.0f / DD);
    float var  = S2 * (1.0f / DD) - mean * mean;
    float rstd = rsqrtf(var + 1e-5f);
    float* o = out + (size_t)row * DD;
#pragma unroll
    for (int k = 0; k < 4; k++) {
        int c = threadIdx.x + k * 256;
        o[c] = (v[k] - mean) * rstd * gg[c] + bb[c];
    }
}

// ==================== SGEMM 128x128x16, 8x8 microtile, fused epilogue =======
// flags: 1 = +bias[col], 2 = +res[row*N+col], 4 = relu
__global__ __launch_bounds__(256, 2)
void sgemm_kernel(int M, int N, int K,
                  const float* __restrict__ A,   // [M,K] row-major
                  const float* __restrict__ Bm,  // [K,N] row-major
                  const float* __restrict__ bias,
                  const float* __restrict__ res,
                  float* __restrict__ C,
                  int flags)
{
    constexpr int BM = 128, BN = 128, BK = 16;
    __shared__ float As[BK][BM];
    __shared__ float Bs[BK][BN];

    int tid = threadIdx.x;
    int tR = tid >> 4;          // 0..15, row group
    int tC = tid & 15;          // 0..15, col group
    int m0 = blockIdx.y * BM;
    int n0 = blockIdx.x * BN;

    float acc[8][8];
#pragma unroll
    for (int i = 0; i < 8; i++)
#pragma unroll
        for (int j = 0; j < 8; j++) acc[i][j] = 0.f;

    for (int k0 = 0; k0 < K; k0 += BK) {
        // load A tile (128x16) transposed into As, and B tile (16x128) into Bs
#pragma unroll
        for (int j = 0; j < 2; j++) {
            int f = tid * 2 + j;                 // 0..511 float4 index
            int ar  = f >> 2;                    // 0..127
            int ac4 = (f & 3) * 4;               // 0,4,8,12
            float4 av = *(const float4*)(A + (size_t)(m0 + ar) * K + k0 + ac4);
            As[ac4 + 0][ar] = av.x;
            As[ac4 + 1][ar] = av.y;
            As[ac4 + 2][ar] = av.z;
            As[ac4 + 3][ar] = av.w;
            int br  = f >> 5;                    // 0..15
            int bc4 = (f & 31) * 4;              // 0..124
            *(float4*)&Bs[br][bc4] =
                *(const float4*)(Bm + (size_t)(k0 + br) * N + n0 + bc4);
        }
        __syncthreads();
#pragma unroll
        for (int kk = 0; kk < BK; kk++) {
            float ra[8], rb[8];
            *(float4*)&ra[0] = *(float4*)&As[kk][tR * 8];
            *(float4*)&ra[4] = *(float4*)&As[kk][tR * 8 + 4];
            *(float4*)&rb[0] = *(float4*)&Bs[kk][tC * 8];
            *(float4*)&rb[4] = *(float4*)&Bs[kk][tC * 8 + 4];
#pragma unroll
            for (int i = 0; i < 8; i++)
#pragma unroll
                for (int j = 0; j < 8; j++)
                    acc[i][j] += ra[i] * rb[j];
        }
        __syncthreads();
    }

    // epilogue
    float bcol[8];
    if (flags & 1) {
#pragma unroll
        for (int j = 0; j < 8; j++) bcol[j] = bias[n0 + tC * 8 + j];
    }
#pragma unroll
    for (int i = 0; i < 8; i++) {
        int row = m0 + tR * 8 + i;
        size_t base = (size_t)row * N + n0 + tC * 8;
        float v[8];
#pragma unroll
        for (int j = 0; j < 8; j++) {
            v[j] = acc[i][j];
            if (flags & 1) v[j] += bcol[j];
        }
        if (flags & 2) {
            float4 r0 = *(const float4*)(res + base);
            float4 r1 = *(const float4*)(res + base + 4);
            v[0] += r0.x; v[1] += r0.y; v[2] += r0.z; v[3] += r0.w;
            v[4] += r1.x; v[5] += r1.y; v[6] += r1.z; v[7] += r1.w;
        }
        if (flags & 4) {
#pragma unroll
            for (int j = 0; j < 8; j++) v[j] = fmaxf(v[j], 0.f);
        }
        *(float4*)(C + base)     = make_float4(v[0], v[1], v[2], v[3]);
        *(float4*)(C + base + 4) = make_float4(v[4], v[5], v[6], v[7]);
    }
}

// ==================== Flash attention (fp32, causal) ========================
// grid: (S/64, H, B), block: 256.  qkv layout: row r=b*S+s, cols [Q|K|V] each
// head-concat (h*64+e).  Output O: [B,S,D] head-concat.
__global__ __launch_bounds__(256)
void attn_kernel(const float* __restrict__ qkv, float* __restrict__ O)
{
    __shared__ float Qt[64 * 64];    // Qt[e][r]  (e-major)
    __shared__ float KtPs[64 * 64];  // phase 1: Kt[e][t]; phase 2: Ps[t][r]
    __shared__ float Vs[64 * 64];    // Vs[t][e]

    int b  = blockIdx.z;
    int h  = blockIdx.y;
    int q0 = blockIdx.x * 64;
    int tid = threadIdx.x;
    int ty = tid >> 4;   // 0..15 row group (rows ty*4 .. ty*4+3)
    int tx = tid & 15;   // 0..15 col group

    // ---- load Q tile transposed ----
#pragma unroll
    for (int j = 0; j < 4; j++) {
        int f  = tid * 4 + j;        // 0..1023 float4 index
        int r  = f >> 4;             // 0..63
        int e4 = (f & 15) * 4;
        float4 v = *(const float4*)(qkv + (size_t)(b * SS + q0 + r) * QKV_N + h * HSZ + e4);
        Qt[(e4 + 0) * 64 + r] = v.x;
        Qt[(e4 + 1) * 64 + r] = v.y;
        Qt[(e4 + 2) * 64 + r] = v.z;
        Qt[(e4 + 3) * 64 + r] = v.w;
    }

    float m_[4], l_[4], o_[4][4];
#pragma unroll
    for (int i = 0; i < 4; i++) {
        m_[i] = -1e30f; l_[i] = 0.f;
#pragma unroll
        for (int j = 0; j < 4; j++) o_[i][j] = 0.f;
    }

    const float scale = 0.125f;      // 1/sqrt(64)
    int ntiles = blockIdx.x + 1;

    for (int jt = 0; jt < ntiles; jt++) {
        int j0 = jt * 64;
        __syncthreads();             // prior-iter reads of KtPs/Vs complete
        // ---- load K (transposed) and V tiles ----
#pragma unroll
        for (int j = 0; j < 4; j++) {
            int f  = tid * 4 + j;
            int t  = f >> 4;
            int e4 = (f & 15) * 4;
            size_t rbase = (size_t)(b * SS + j0 + t) * QKV_N + h * HSZ + e4;
            float4 kv = *(const float4*)(qkv + rbase + DD);
            KtPs[(e4 + 0) * 64 + t] = kv.x;
            KtPs[(e4 + 1) * 64 + t] = kv.y;
            KtPs[(e4 + 2) * 64 + t] = kv.z;
            KtPs[(e4 + 3) * 64 + t] = kv.w;
            *(float4*)&Vs[t * 64 + e4] = *(const float4*)(qkv + rbase + 2 * DD);
        }
        __syncthreads();

        // ---- scores S = Q K^T (4x4 per thread) ----
        float s[4][4];
#pragma unroll
        for (int i = 0; i < 4; i++)
#pragma unroll
            for (int j = 0; j < 4; j++) s[i][j] = 0.f;
#pragma unroll 4
        for (int e = 0; e < 64; e++) {
            float4 qa = *(float4*)&Qt[e * 64 + ty * 4];
            float4 ka = *(float4*)&KtPs[e * 64 + tx * 4];
            float qv[4] = {qa.x, qa.y, qa.z, qa.w};
            float kv[4] = {ka.x, ka.y, ka.z, ka.w};
#pragma unroll
            for (int i = 0; i < 4; i++)
#pragma unroll
                for (int j = 0; j < 4; j++)
                    s[i][j] += qv[i] * kv[j];
        }
        bool diag = (j0 == q0);
#pragma unroll
        for (int i = 0; i < 4; i++) {
            int qr = q0 + ty * 4 + i;
#pragma unroll
            for (int j = 0; j < 4; j++) {
                s[i][j] *= scale;
                if (diag && (j0 + tx * 4 + j) > qr) s[i][j] = -1e30f;
            }
        }
        __syncthreads();             // all Kt reads done; KtPs becomes Ps

        // ---- online softmax update + write P ----
#pragma unroll
        for (int i = 0; i < 4; i++) {
            float mt = fmaxf(fmaxf(s[i][0], s[i][1]), fmaxf(s[i][2], s[i][3]));
#pragma unroll
            for (int off = 8; off; off >>= 1)
                mt = fmaxf(mt, __shfl_xor_sync(0xffffffffu, mt, off));
            float newm  = fmaxf(m_[i], mt);
            float alpha = __expf(m_[i] - newm);
            m_[i] = newm;
            float p[4], psum = 0.f;
#pragma unroll
            for (int j = 0; j < 4; j++) {
                p[j] = __expf(s[i][j] - newm);
                psum += p[j];
            }
#pragma unroll
            for (int off = 8; off; off >>= 1)
                psum += __shfl_xor_sync(0xffffffffu, psum, off);
            l_[i] = l_[i] * alpha + psum;
#pragma unroll
            for (int j = 0; j < 4; j++) {
                o_[i][j] *= alpha;
                KtPs[(tx * 4 + j) * 64 + (ty * 4 + i)] = p[j];  // Ps[t][r]
            }
        }
        __syncthreads();

        // ---- O += P V ----
#pragma unroll 4
        for (int t = 0; t < 64; t++) {
            float4 pr = *(float4*)&KtPs[t * 64 + ty * 4];
            float4 vr = *(float4*)&Vs[t * 64 + tx * 4];
            float pv[4] = {pr.x, pr.y, pr.z, pr.w};
            float vv[4] = {vr.x, vr.y, vr.z, vr.w};
#pragma unroll
            for (int i = 0; i < 4; i++)
#pragma unroll
                for (int j = 0; j < 4; j++)
                    o_[i][j] += pv[i] * vv[j];
        }
    }

    // ---- finalize + write ----
#pragma unroll
    for (int i = 0; i < 4; i++) {
        float inv = 1.0f / l_[i];
        float4 out = make_float4(o_[i][0] * inv, o_[i][1] * inv,
                                 o_[i][2] * inv, o_[i][3] * inv);
        size_t idx = (size_t)(b * SS + q0 + ty * 4 + i) * DD + h * HSZ + tx * 4;
        *(float4*)&O[idx] = out;
    }
}

// ==================== host launcher ========================================
extern "C" void kernel_launch(void* const* d_in, const int* in_sizes, int n_in,
                              void* d_out, int out_size)
{
    const float* x      = (const float*)d_in[0];
    const float* wq     = (const float*)d_in[1];
    const float* wk     = (const float*)d_in[2];
    const float* wv     = (const float*)d_in[3];
    const float* proj_w = (const float*)d_in[4];
    const float* proj_b = (const float*)d_in[5];
    const float* ff1_w  = (const float*)d_in[6];
    const float* ff1_b  = (const float*)d_in[7];
    const float* ff2_w  = (const float*)d_in[8];
    const float* ff2_b  = (const float*)d_in[9];
    const float* ln1_g  = (const float*)d_in[10];
    const float* ln1_b  = (const float*)d_in[11];
    const float* ln2_g  = (const float*)d_in[12];
    const float* ln2_b  = (const float*)d_in[13];
    float* out = (float*)d_out;

    // Resolve scratch addresses once (capture-safe: no alloc, no sync, but
    // hoisting avoids repeated runtime-API calls during graph capture).
    static float *h = nullptr, *qkv, *wpack, *o, *ffh;
    if (!h) {
        cudaGetSymbolAddress((void**)&h,     g_h);
        cudaGetSymbolAddress((void**)&qkv,   g_qkv);
        cudaGetSymbolAddress((void**)&wpack, g_wqkv);
        cudaGetSymbolAddress((void**)&o,     g_o);
        cudaGetSymbolAddress((void**)&ffh,   g_ffh);
    }

    // 1. pack qkv weights
    repack_kernel<<<(DD * QKV_N + 255) / 256, 256>>>(wq, wk, wv, wpack);
    // 2. h = LN1(x)
    ln_kernel<<<NROWS, 256>>>(x, ln1_g, ln1_b, h);
    // 3. qkv = h @ Wqkv            [8192,1024] x [1024,3072]
    sgemm_kernel<<<dim3(QKV_N / 128, NROWS / 128), 256>>>(
        NROWS, QKV_N, DD, h, wpack, nullptr, nullptr, qkv, 0);
    // 4. flash attention -> o (head-concat)
    attn_kernel<<<dim3(SS / 64, HH, BB), 256>>>(qkv, o);
    // 5. out = x + o @ proj_w + proj_b
    sgemm_kernel<<<dim3(DD / 128, NROWS / 128), 256>>>(
        NROWS, DD, DD, o, proj_w, proj_b, x, out, 1 | 2);
    // 6. h = LN2(out)
    ln_kernel<<<NROWS, 256>>>(out, ln2_g, ln2_b, h);
    // 7. ffh = relu(h @ ff1_w + ff1_b)
    sgemm_kernel<<<dim3(DFF / 128, NROWS / 128), 256>>>(
        NROWS, DFF, DD, h, ff1_w, ff1_b, nullptr, ffh, 1 | 4);
    // 8. out += ffh @ ff2_w + ff2_b
    sgemm_kernel<<<dim3(DD / 128, NROWS / 128), 256>>>(
        NROWS, DD, DFF, ffh, ff2_w, ff2_b, out, out, 1 | 2);
}

// round 3
// speedup vs baseline: 1.9110x; 1.9110x over previous
#include <cuda_runtime.h>
#include <cuda_bf16.h>
#include <math.h>
#include <stdint.h>

// ---------------- problem constants ----------------
#define BB 4
#define SS 2048
#define DD 1024
#define HH 16
#define HSZ 64
#define DFF 4096
#define NROWS (BB * SS)          // 8192
#define QKV_N (3 * DD)           // 3072

// ---------------- scratch (static device globals; no cudaMalloc allowed) ----
__device__ float g_h[NROWS * DD];        // LN output (reused for ln1 and ln2)
__device__ float g_qkv[NROWS * QKV_N];   // Q|K|V, head-concat per row
__device__ float g_wqkv[DD * QKV_N];     // packed qkv weights [d][n]
__device__ float g_o[NROWS * DD];        // attention output (head-concat)
__device__ float g_ffh[NROWS * DFF];     // FFN hidden

// ==================== weight repack: wq/wk/wv [H,D,HS] -> W[d][n] ===========
__global__ void repack_kernel(const float* __restrict__ wq,
                              const float* __restrict__ wk,
                              const float* __restrict__ wv,
                              float* __restrict__ W)
{
    int idx = blockIdx.x * 256 + threadIdx.x;
    if (idx >= DD * QKV_N) return;
    int d = idx / QKV_N;
    int n = idx % QKV_N;
    int sel = n >> 10;          // 0:q 1:k 2:v
    int nn  = n & 1023;
    int hh  = nn >> 6;
    int e   = nn & 63;
    const float* src = (sel == 0) ? wq : (sel == 1) ? wk : wv;
    W[idx] = src[((size_t)hh * DD + d) * HSZ + e];
}

// ==================== LayerNorm: one block per row (1024 cols) ==============
__global__ void ln_kernel(const float* __restrict__ in,
                          const float* __restrict__ gg,
                          const float* __restrict__ bb,
                          float* __restrict__ out)
{
    int row = blockIdx.x;
    const float* x = in + (size_t)row * DD;
    float v[4];
    float s = 0.f, s2 = 0.f;
#pragma unroll
    for (int k = 0; k < 4; k++) {
        v[k] = x[threadIdx.x + k * 256];
        s  += v[k];
        s2 += v[k] * v[k];
    }
#pragma unroll
    for (int off = 16; off; off >>= 1) {
        s  += __shfl_xor_sync(0xffffffffu, s,  off);
        s2 += __shfl_xor_sync(0xffffffffu, s2, off);
    }
    __shared__ float red[2][8];
    int wid = threadIdx.x >> 5, lane = threadIdx.x & 31;
    if (lane == 0) { red[0][wid] = s; red[1][wid] = s2; }
    __syncthreads();
    float S = 0.f, S2 = 0.f;
#pragma unroll
    for (int w = 0; w < 8; w++) { S += red[0][w]; S2 += red[1][w]; }
    float mean = S * (1.0f / DD);
    float var  = S2 * (1.0f / DD) - mean * mean;
    float rstd = rsqrtf(var + 1e-5f);
    float* o = out + (size_t)row * DD;
#pragma unroll
    for (int k = 0; k < 4; k++) {
        int c = threadIdx.x + k * 256;
        o[c] = (v[k] - mean) * rstd * gg[c] + bb[c];
    }
}

// ==================== TF32 tensor-core GEMM =================================
// C[M,N] = A[M,K] @ B[K,N], tile 128x128x32, 8 warps (2x4), warp tile 64x32.
// flags: 1 = +bias[col], 2 = +res[row*N+col], 4 = relu
__device__ __forceinline__ uint32_t f2tf32(float x) {
    uint32_t t;
    asm("cvt.rna.tf32.f32 %0, %1;" : "=r"(t) : "f"(x));
    return t;
}

__device__ __forceinline__ void mma_tf32(float* c, const uint32_t* a,
                                         const uint32_t* b) {
    asm volatile(
        "mma.sync.aligned.m16n8k8.row.col.f32.tf32.tf32.f32 "
        "{%0,%1,%2,%3}, {%4,%5,%6,%7}, {%8,%9}, {%0,%1,%2,%3};\n"
        : "+f"(c[0]), "+f"(c[1]), "+f"(c[2]), "+f"(c[3])
        : "r"(a[0]), "r"(a[1]), "r"(a[2]), "r"(a[3]),
          "r"(b[0]), "r"(b[1]));
}

__global__ __launch_bounds__(256, 2)
void tf32gemm_kernel(int M, int N, int K,
                     const float* __restrict__ A,   // [M,K]
                     const float* __restrict__ Bm,  // [K,N]
                     const float* __restrict__ bias,
                     const float* __restrict__ res,
                     float* __restrict__ C,
                     int flags)
{
    constexpr int BM = 128, BN = 128, BK = 32;
    // As: [row][k], row stride 36 words -> fragment-load word = 4*row + k (mod 32)
    // Bs: [k][n],   k stride 136 words  -> fragment-load word = 8*k + n (mod 32)
    __shared__ uint32_t As[BM * 36];
    __shared__ uint32_t Bs[BK * 136];

    int tid  = threadIdx.x;
    int lane = tid & 31;
    int warp = tid >> 5;
    int g    = lane >> 2;       // group id 0..7
    int tig  = lane & 3;        // thread in group 0..3
    int warp_m = warp & 1;      // 0..1  -> 64-row slab
    int warp_n = warp >> 1;     // 0..3  -> 32-col slab
    int m0 = blockIdx.y * BM;
    int n0 = blockIdx.x * BN;

    // gmem->smem assignments
    int arow = tid >> 1;               // 0..127
    int acol = (tid & 1) * 16;         // 0 or 16
    int brow = tid >> 3;               // 0..31
    int bcol = (tid & 7) * 4;          // 0..28 (q adds 32 each)

    float acc[4][4][4];
#pragma unroll
    for (int i = 0; i < 4; i++)
#pragma unroll
        for (int j = 0; j < 4; j++)
#pragma unroll
            for (int c = 0; c < 4; c++) acc[i][j][c] = 0.f;

    const float* aptr = A + (size_t)(m0 + arow) * K + acol;
    const float* bptr = Bm + (size_t)brow * N + n0 + bcol;

    for (int k0 = 0; k0 < K; k0 += BK) {
        // ---- load A tile (128x32) ----
#pragma unroll
        for (int q = 0; q < 4; q++) {
            float4 v = *(const float4*)(aptr + k0 + q * 4);
            uint4 t;
            t.x = f2tf32(v.x); t.y = f2tf32(v.y);
            t.z = f2tf32(v.z); t.w = f2tf32(v.w);
            *(uint4*)&As[arow * 36 + acol + q * 4] = t;
        }
        // ---- load B tile (32x128) ----
#pragma unroll
        for (int q = 0; q < 4; q++) {
            float4 v = *(const float4*)(bptr + (size_t)k0 * N + q * 32);
            uint4 t;
            t.x = f2tf32(v.x); t.y = f2tf32(v.y);
            t.z = f2tf32(v.z); t.w = f2tf32(v.w);
            *(uint4*)&Bs[brow * 136 + bcol + q * 32] = t;
        }
        __syncthreads();

#pragma unroll
        for (int ks = 0; ks < 4; ks++) {
            int kb = ks * 8;
            uint32_t afr[4][4], bfr[4][2];
#pragma unroll
            for (int i = 0; i < 4; i++) {
                int r = warp_m * 64 + i * 16 + g;
                afr[i][0] = As[r * 36 + kb + tig];
                afr[i][1] = As[(r + 8) * 36 + kb + tig];
                afr[i][2] = As[r * 36 + kb + tig + 4];
                afr[i][3] = As[(r + 8) * 36 + kb + tig + 4];
            }
#pragma unroll
            for (int j = 0; j < 4; j++) {
                int n = warp_n * 32 + j * 8 + g;
                bfr[j][0] = Bs[(kb + tig) * 136 + n];
                bfr[j][1] = Bs[(kb + tig + 4) * 136 + n];
            }
#pragma unroll
            for (int i = 0; i < 4; i++)
#pragma unroll
                for (int j = 0; j < 4; j++)
                    mma_tf32(acc[i][j], afr[i], bfr[j]);
        }
        __syncthreads();
    }

    // ---- epilogue: c0,c1 -> (r, col..col+1), c2,c3 -> (r+8, col..col+1) ----
#pragma unroll
    for (int j = 0; j < 4; j++) {
        int col = n0 + warp_n * 32 + j * 8 + 2 * tig;
        float b0 = 0.f, b1 = 0.f;
        if (flags & 1) { b0 = bias[col]; b1 = bias[col + 1]; }
#pragma unroll
        for (int i = 0; i < 4; i++) {
            int r = m0 + warp_m * 64 + i * 16 + g;
#pragma unroll
            for (int half = 0; half < 2; half++) {
                int row = r + half * 8;
                size_t base = (size_t)row * N + col;
                float v0 = acc[i][j][half * 2 + 0] + b0;
                float v1 = acc[i][j][half * 2 + 1] + b1;
                if (flags & 2) {
                    float2 rr = *(const float2*)(res + base);
                    v0 += rr.x; v1 += rr.y;
                }
                if (flags & 4) { v0 = fmaxf(v0, 0.f); v1 = fmaxf(v1, 0.f); }
                *(float2*)(C + base) = make_float2(v0, v1);
            }
        }
    }
}

// ==================== Flash attention (fp32, causal) ========================
__global__ __launch_bounds__(256)
void attn_kernel(const float* __restrict__ qkv, float* __restrict__ O)
{
    __shared__ float Qt[64 * 64];    // Qt[e][r]  (e-major)
    __shared__ float KtPs[64 * 64];  // phase 1: Kt[e][t]; phase 2: Ps[t][r]
    __shared__ float Vs[64 * 64];    // Vs[t][e]

    int b  = blockIdx.z;
    int h  = blockIdx.y;
    int q0 = blockIdx.x * 64;
    int tid = threadIdx.x;
    int ty = tid >> 4;   // 0..15 row group
    int tx = tid & 15;   // 0..15 col group

#pragma unroll
    for (int j = 0; j < 4; j++) {
        int f  = tid * 4 + j;
        int r  = f >> 4;
        int e4 = (f & 15) * 4;
        float4 v = *(const float4*)(qkv + (size_t)(b * SS + q0 + r) * QKV_N + h * HSZ + e4);
        Qt[(e4 + 0) * 64 + r] = v.x;
        Qt[(e4 + 1) * 64 + r] = v.y;
        Qt[(e4 + 2) * 64 + r] = v.z;
        Qt[(e4 + 3) * 64 + r] = v.w;
    }

    float m_[4], l_[4], o_[4][4];
#pragma unroll
    for (int i = 0; i < 4; i++) {
        m_[i] = -1e30f; l_[i] = 0.f;
#pragma unroll
        for (int j = 0; j < 4; j++) o_[i][j] = 0.f;
    }

    const float scale = 0.125f;
    int ntiles = blockIdx.x + 1;

    for (int jt = 0; jt < ntiles; jt++) {
        int j0 = jt * 64;
        __syncthreads();
#pragma unroll
        for (int j = 0; j < 4; j++) {
            int f  = tid * 4 + j;
            int t  = f >> 4;
            int e4 = (f & 15) * 4;
            size_t rbase = (size_t)(b * SS + j0 + t) * QKV_N + h * HSZ + e4;
            float4 kv = *(const float4*)(qkv + rbase + DD);
            KtPs[(e4 + 0) * 64 + t] = kv.x;
            KtPs[(e4 + 1) * 64 + t] = kv.y;
            KtPs[(e4 + 2) * 64 + t] = kv.z;
            KtPs[(e4 + 3) * 64 + t] = kv.w;
            *(float4*)&Vs[t * 64 + e4] = *(const float4*)(qkv + rbase + 2 * DD);
        }
        __syncthreads();

        float s[4][4];
#pragma unroll
        for (int i = 0; i < 4; i++)
#pragma unroll
            for (int j = 0; j < 4; j++) s[i][j] = 0.f;
#pragma unroll 4
        for (int e = 0; e < 64; e++) {
            float4 qa = *(float4*)&Qt[e * 64 + ty * 4];
            float4 ka = *(float4*)&KtPs[e * 64 + tx * 4];
            float qv[4] = {qa.x, qa.y, qa.z, qa.w};
            float kv[4] = {ka.x, ka.y, ka.z, ka.w};
#pragma unroll
            for (int i = 0; i < 4; i++)
#pragma unroll
                for (int j = 0; j < 4; j++)
                    s[i][j] += qv[i] * kv[j];
        }
        bool diag = (j0 == q0);
#pragma unroll
        for (int i = 0; i < 4; i++) {
            int qr = q0 + ty * 4 + i;
#pragma unroll
            for (int j = 0; j < 4; j++) {
                s[i][j] *= scale;
                if (diag && (j0 + tx * 4 + j) > qr) s[i][j] = -1e30f;
            }
        }
        __syncthreads();

#pragma unroll
        for (int i = 0; i < 4; i++) {
            float mt = fmaxf(fmaxf(s[i][0], s[i][1]), fmaxf(s[i][2], s[i][3]));
#pragma unroll
            for (int off = 8; off; off >>= 1)
                mt = fmaxf(mt, __shfl_xor_sync(0xffffffffu, mt, off));
            float newm  = fmaxf(m_[i], mt);
            float alpha = __expf(m_[i] - newm);
            m_[i] = newm;
            float p[4], psum = 0.f;
#pragma unroll
            for (int j = 0; j < 4; j++) {
                p[j] = __expf(s[i][j] - newm);
                psum += p[j];
            }
#pragma unroll
            for (int off = 8; off; off >>= 1)
                psum += __shfl_xor_sync(0xffffffffu, psum, off);
            l_[i] = l_[i] * alpha + psum;
#pragma unroll
            for (int j = 0; j < 4; j++) {
                o_[i][j] *= alpha;
                KtPs[(tx * 4 + j) * 64 + (ty * 4 + i)] = p[j];
            }
        }
        __syncthreads();

#pragma unroll 4
        for (int t = 0; t < 64; t++) {
            float4 pr = *(float4*)&KtPs[t * 64 + ty * 4];
            float4 vr = *(float4*)&Vs[t * 64 + tx * 4];
            float pv[4] = {pr.x, pr.y, pr.z, pr.w};
            float vv[4] = {vr.x, vr.y, vr.z, vr.w};
#pragma unroll
            for (int i = 0; i < 4; i++)
#pragma unroll
                for (int j = 0; j < 4; j++)
                    o_[i][j] += pv[i] * vv[j];
        }
    }

#pragma unroll
    for (int i = 0; i < 4; i++) {
        float inv = 1.0f / l_[i];
        float4 out = make_float4(o_[i][0] * inv, o_[i][1] * inv,
                                 o_[i][2] * inv, o_[i][3] * inv);
        size_t idx = (size_t)(b * SS + q0 + ty * 4 + i) * DD + h * HSZ + tx * 4;
        *(float4*)&O[idx] = out;
    }
}

// ==================== host launcher ========================================
extern "C" void kernel_launch(void* const* d_in, const int* in_sizes, int n_in,
                              void* d_out, int out_size)
{
    const float* x      = (const float*)d_in[0];
    const float* wq     = (const float*)d_in[1];
    const float* wk     = (const float*)d_in[2];
    const float* wv     = (const float*)d_in[3];
    const float* proj_w = (const float*)d_in[4];
    const float* proj_b = (const float*)d_in[5];
    const float* ff1_w  = (const float*)d_in[6];
    const float* ff1_b  = (const float*)d_in[7];
    const float* ff2_w  = (const float*)d_in[8];
    const float* ff2_b  = (const float*)d_in[9];
    const float* ln1_g  = (const float*)d_in[10];
    const float* ln1_b  = (const float*)d_in[11];
    const float* ln2_g  = (const float*)d_in[12];
    const float* ln2_b  = (const float*)d_in[13];
    float* out = (float*)d_out;

    static float *h = nullptr, *qkv, *wpack, *o, *ffh;
    if (!h) {
        cudaGetSymbolAddress((void**)&h,     g_h);
        cudaGetSymbolAddress((void**)&qkv,   g_qkv);
        cudaGetSymbolAddress((void**)&wpack, g_wqkv);
        cudaGetSymbolAddress((void**)&o,     g_o);
        cudaGetSymbolAddress((void**)&ffh,   g_ffh);
    }

    // 1. pack qkv weights
    repack_kernel<<<(DD * QKV_N + 255) / 256, 256>>>(wq, wk, wv, wpack);
    // 2. h = LN1(x)
    ln_kernel<<<NROWS, 256>>>(x, ln1_g, ln1_b, h);
    // 3. qkv = h @ Wqkv            [8192,1024] x [1024,3072]
    tf32gemm_kernel<<<dim3(QKV_N / 128, NROWS / 128), 256>>>(
        NROWS, QKV_N, DD, h, wpack, nullptr, nullptr, qkv, 0);
    // 4. flash attention -> o (head-concat)
    attn_kernel<<<dim3(SS / 64, HH, BB), 256>>>(qkv, o);
    // 5. out = x + o @ proj_w + proj_b
    tf32gemm_kernel<<<dim3(DD / 128, NROWS / 128), 256>>>(
        NROWS, DD, DD, o, proj_w, proj_b, x, out, 1 | 2);
    // 6. h = LN2(out)
    ln_kernel<<<NROWS, 256>>>(out, ln2_g, ln2_b, h);
    // 7. ffh = relu(h @ ff1_w + ff1_b)
    tf32gemm_kernel<<<dim3(DFF / 128, NROWS / 128), 256>>>(
        NROWS, DFF, DD, h, ff1_w, ff1_b, nullptr, ffh, 1 | 4);
    // 8. out += ffh @ ff2_w + ff2_b
    tf32gemm_kernel<<<dim3(DD / 128, NROWS / 128), 256>>>(
        NROWS, DD, DFF, ffh, ff2_w, ff2_b, out, out, 1 | 2);
}

// round 5
// speedup vs baseline: 2.8023x; 1.4664x over previous
#include <cuda_runtime.h>
#include <cuda_bf16.h>
#include <math.h>
#include <stdint.h>

// ---------------- problem constants ----------------
#define BB 4
#define SS 2048
#define DD 1024
#define HH 16
#define HSZ 64
#define DFF 4096
#define NROWS (BB * SS)          // 8192
#define QKV_N (3 * DD)           // 3072

// ---------------- scratch (static device globals; no cudaMalloc allowed) ----
__device__ float g_h[NROWS * DD];        // LN output (reused for ln1 and ln2)
__device__ float g_qkv[NROWS * QKV_N];   // Q|K|V, head-concat per row
__device__ float g_wqkv[DD * QKV_N];     // packed qkv weights [d][n]
__device__ float g_o[NROWS * DD];        // attention output (head-concat)
__device__ float g_ffh[NROWS * DFF];     // FFN hidden

// ==================== helpers ==============================================
__device__ __forceinline__ uint32_t f2tf32(float x) {
    uint32_t t;
    asm("cvt.rna.tf32.f32 %0, %1;" : "=r"(t) : "f"(x));
    return t;
}
__device__ __forceinline__ void mma_tf32(float* c, const uint32_t* a,
                                         const uint32_t* b) {
    asm volatile(
        "mma.sync.aligned.m16n8k8.row.col.f32.tf32.tf32.f32 "
        "{%0,%1,%2,%3}, {%4,%5,%6,%7}, {%8,%9}, {%0,%1,%2,%3};\n"
        : "+f"(c[0]), "+f"(c[1]), "+f"(c[2]), "+f"(c[3])
        : "r"(a[0]), "r"(a[1]), "r"(a[2]), "r"(a[3]),
          "r"(b[0]), "r"(b[1]));
}

// ==================== weight repack: wq/wk/wv [H,D,HS] -> W[d][n] ===========
__global__ void repack_kernel(const float* __restrict__ wq,
                              const float* __restrict__ wk,
                              const float* __restrict__ wv,
                              float* __restrict__ W)
{
    int idx = blockIdx.x * 256 + threadIdx.x;
    if (idx >= DD * QKV_N) return;
    int d = idx / QKV_N;
    int n = idx % QKV_N;
    int sel = n >> 10;
    int nn  = n & 1023;
    int hh  = nn >> 6;
    int e   = nn & 63;
    const float* src = (sel == 0) ? wq : (sel == 1) ? wk : wv;
    W[idx] = src[((size_t)hh * DD + d) * HSZ + e];
}

// ==================== LayerNorm: one block per row (1024 cols) ==============
__global__ void ln_kernel(const float* __restrict__ in,
                          const float* __restrict__ gg,
                          const float* __restrict__ bb,
                          float* __restrict__ out)
{
    int row = blockIdx.x;
    const float* x = in + (size_t)row * DD;
    float v[4];
    float s = 0.f, s2 = 0.f;
#pragma unroll
    for (int k = 0; k < 4; k++) {
        v[k] = x[threadIdx.x + k * 256];
        s  += v[k];
        s2 += v[k] * v[k];
    }
#pragma unroll
    for (int off = 16; off; off >>= 1) {
        s  += __shfl_xor_sync(0xffffffffu, s,  off);
        s2 += __shfl_xor_sync(0xffffffffu, s2, off);
    }
    __shared__ float red[2][8];
    int wid = threadIdx.x >> 5, lane = threadIdx.x & 31;
    if (lane == 0) { red[0][wid] = s; red[1][wid] = s2; }
    __syncthreads();
    float S = 0.f, S2 = 0.f;
#pragma unroll
    for (int w = 0; w < 8; w++) { S += red[0][w]; S2 += red[1][w]; }
    float mean = S * (1.0f / DD);
    float var  = S2 * (1.0f / DD) - mean * mean;
    float rstd = rsqrtf(var + 1e-5f);
    float* o = out + (size_t)row * DD;
#pragma unroll
    for (int k = 0; k < 4; k++) {
        int c = threadIdx.x + k * 256;
        o[c] = (v[k] - mean) * rstd * gg[c] + bb[c];
    }
}

// ==================== TF32 tensor-core GEMM =================================
__global__ __launch_bounds__(256, 2)
void tf32gemm_kernel(int M, int N, int K,
                     const float* __restrict__ A,
                     const float* __restrict__ Bm,
                     const float* __restrict__ bias,
                     const float* __restrict__ res,
                     float* __restrict__ C,
                     int flags)
{
    constexpr int BM = 128, BN = 128, BK = 32;
    __shared__ uint32_t As[BM * 36];
    __shared__ uint32_t Bs[BK * 136];

    int tid  = threadIdx.x;
    int lane = tid & 31;
    int warp = tid >> 5;
    int g    = lane >> 2;
    int tig  = lane & 3;
    int warp_m = warp & 1;
    int warp_n = warp >> 1;
    int m0 = blockIdx.y * BM;
    int n0 = blockIdx.x * BN;

    int arow = tid >> 1;
    int acol = (tid & 1) * 16;
    int brow = tid >> 3;
    int bcol = (tid & 7) * 4;

    float acc[4][4][4];
#pragma unroll
    for (int i = 0; i < 4; i++)
#pragma unroll
        for (int j = 0; j < 4; j++)
#pragma unroll
            for (int c = 0; c < 4; c++) acc[i][j][c] = 0.f;

    const float* aptr = A + (size_t)(m0 + arow) * K + acol;
    const float* bptr = Bm + (size_t)brow * N + n0 + bcol;

    for (int k0 = 0; k0 < K; k0 += BK) {
#pragma unroll
        for (int q = 0; q < 4; q++) {
            float4 v = *(const float4*)(aptr + k0 + q * 4);
            uint4 t;
            t.x = f2tf32(v.x); t.y = f2tf32(v.y);
            t.z = f2tf32(v.z); t.w = f2tf32(v.w);
            *(uint4*)&As[arow * 36 + acol + q * 4] = t;
        }
#pragma unroll
        for (int q = 0; q < 4; q++) {
            float4 v = *(const float4*)(bptr + (size_t)k0 * N + q * 32);
            uint4 t;
            t.x = f2tf32(v.x); t.y = f2tf32(v.y);
            t.z = f2tf32(v.z); t.w = f2tf32(v.w);
            *(uint4*)&Bs[brow * 136 + bcol + q * 32] = t;
        }
        __syncthreads();

#pragma unroll
        for (int ks = 0; ks < 4; ks++) {
            int kb = ks * 8;
            uint32_t afr[4][4], bfr[4][2];
#pragma unroll
            for (int i = 0; i < 4; i++) {
                int r = warp_m * 64 + i * 16 + g;
                afr[i][0] = As[r * 36 + kb + tig];
                afr[i][1] = As[(r + 8) * 36 + kb + tig];
                afr[i][2] = As[r * 36 + kb + tig + 4];
                afr[i][3] = As[(r + 8) * 36 + kb + tig + 4];
            }
#pragma unroll
            for (int j = 0; j < 4; j++) {
                int n = warp_n * 32 + j * 8 + g;
                bfr[j][0] = Bs[(kb + tig) * 136 + n];
                bfr[j][1] = Bs[(kb + tig + 4) * 136 + n];
            }
#pragma unroll
            for (int i = 0; i < 4; i++)
#pragma unroll
                for (int j = 0; j < 4; j++)
                    mma_tf32(acc[i][j], afr[i], bfr[j]);
        }
        __syncthreads();
    }

#pragma unroll
    for (int j = 0; j < 4; j++) {
        int col = n0 + warp_n * 32 + j * 8 + 2 * tig;
        float b0 = 0.f, b1 = 0.f;
        if (flags & 1) { b0 = bias[col]; b1 = bias[col + 1]; }
#pragma unroll
        for (int i = 0; i < 4; i++) {
            int r = m0 + warp_m * 64 + i * 16 + g;
#pragma unroll
            for (int half = 0; half < 2; half++) {
                int row = r + half * 8;
                size_t base = (size_t)row * N + col;
                float v0 = acc[i][j][half * 2 + 0] + b0;
                float v1 = acc[i][j][half * 2 + 1] + b1;
                if (flags & 2) {
                    float2 rr = *(const float2*)(res + base);
                    v0 += rr.x; v1 += rr.y;
                }
                if (flags & 4) { v0 = fmaxf(v0, 0.f); v1 = fmaxf(v1, 0.f); }
                *(float2*)(C + base) = make_float2(v0, v1);
            }
        }
    }
}

// ==================== TF32 tensor-core flash attention ======================
// CTA: 128 q-rows, 8 warps, each warp owns 16 rows x 64 cols. K-tile = 64.
// Smem (dynamic):
//   Qs [128][68] tf32   (A-pattern, stride%32==4 -> conflict-free a-frags)
//   KP [128][68]        phase1: Ks[t][e] (64 rows; B-frags via n-major = A-pattern)
//                       phase2: Ps[r][t] (A operand of P@V)
//   Vs [64][72]  tf32   (k-major B operand, stride%32==8 -> conflict-free)
#define ATT_SMEM_BYTES ((128*68 + 128*68 + 64*72) * 4)

__global__ __launch_bounds__(256, 2)
void attn_tc_kernel(const float* __restrict__ qkv, float* __restrict__ O)
{
    extern __shared__ uint32_t sm[];
    uint32_t* Qs = sm;                   // [128][68]
    uint32_t* KP = sm + 128 * 68;        // Ks[64][68] / Ps[128][68]
    uint32_t* Vs = sm + 2 * 128 * 68;    // [64][72]

    int b  = blockIdx.z;
    int h  = blockIdx.y;
    int q0 = blockIdx.x * 128;
    int tid  = threadIdx.x;
    int lane = tid & 31, warp = tid >> 5;
    int g    = lane >> 2, tig = lane & 3;

    // ---- load Q tile (128x64) -> Qs (tf32) ----
    {
        int r  = tid >> 1;
        int c0 = (tid & 1) * 32;
        const float* src = qkv + (size_t)(b * SS + q0 + r) * QKV_N + h * HSZ + c0;
#pragma unroll
        for (int q = 0; q < 8; q++) {
            float4 v = *(const float4*)(src + q * 4);
            uint4 t;
            t.x = f2tf32(v.x); t.y = f2tf32(v.y);
            t.z = f2tf32(v.z); t.w = f2tf32(v.w);
            *(uint4*)&Qs[r * 68 + c0 + q * 4] = t;
        }
    }

    float o_[8][4];
#pragma unroll
    for (int n = 0; n < 8; n++)
#pragma unroll
        for (int c = 0; c < 4; c++) o_[n][c] = 0.f;
    float m0 = -1e30f, m8 = -1e30f, l0 = 0.f, l8 = 0.f;

    int Rw   = q0 + warp * 16;       // warp's first row
    int row0 = Rw + g;               // rows row0 and row0+8
    int rmax = Rw + 15;
    int rloc = warp * 16 + g;        // local row in tile

    int ntile = 2 * blockIdx.x + 2;
    for (int jt = 0; jt < ntile; jt++) {
        int j0 = jt * 64;
        __syncthreads();             // prior-iter Ps/Vs reads complete
        // ---- load K,V tiles (64x64 each) ----
        {
            int t  = tid >> 2;
            int c0 = (tid & 3) * 16;
            const float* kp = qkv + (size_t)(b * SS + j0 + t) * QKV_N + DD + h * HSZ + c0;
#pragma unroll
            for (int q = 0; q < 4; q++) {
                float4 v = *(const float4*)(kp + q * 4);
                uint4 tk;
                tk.x = f2tf32(v.x); tk.y = f2tf32(v.y);
                tk.z = f2tf32(v.z); tk.w = f2tf32(v.w);
                *(uint4*)&KP[t * 68 + c0 + q * 4] = tk;
                float4 w = *(const float4*)(kp + DD + q * 4);
                uint4 tv;
                tv.x = f2tf32(w.x); tv.y = f2tf32(w.y);
                tv.z = f2tf32(w.z); tv.w = f2tf32(w.w);
                *(uint4*)&Vs[t * 72 + c0 + q * 4] = tv;
            }
        }
        __syncthreads();

        bool active = (j0 <= rmax);
        float p[8][4];
        if (active) {
            // ---- S = Q K^T (16x64 per warp) ----
#pragma unroll
            for (int n = 0; n < 8; n++)
#pragma unroll
                for (int c = 0; c < 4; c++) p[n][c] = 0.f;
#pragma unroll
            for (int ks = 0; ks < 8; ks++) {
                int kb = ks * 8;
                uint32_t a[4];
                a[0] = Qs[rloc * 68 + kb + tig];
                a[1] = Qs[(rloc + 8) * 68 + kb + tig];
                a[2] = Qs[rloc * 68 + kb + tig + 4];
                a[3] = Qs[(rloc + 8) * 68 + kb + tig + 4];
#pragma unroll
                for (int n = 0; n < 8; n++) {
                    uint32_t bf[2];
                    bf[0] = KP[(n * 8 + g) * 68 + kb + tig];
                    bf[1] = KP[(n * 8 + g) * 68 + kb + tig + 4];
                    mma_tf32(p[n], a, bf);
                }
            }
            // ---- scale + causal mask + row max ----
            bool needmask = (j0 + 63 > Rw);
            float mt0 = -1e30f, mt8 = -1e30f;
#pragma unroll
            for (int n = 0; n < 8; n++) {
#pragma unroll
                for (int c = 0; c < 4; c++) {
                    float v = p[n][c] * 0.125f;
                    if (needmask) {
                        int col = j0 + n * 8 + 2 * tig + (c & 1);
                        int row = row0 + (c >> 1) * 8;
                        if (col > row) v = -1e30f;
                    }
                    p[n][c] = v;
                    if (c < 2) mt0 = fmaxf(mt0, v); else mt8 = fmaxf(mt8, v);
                }
            }
            mt0 = fmaxf(mt0, __shfl_xor_sync(0xffffffffu, mt0, 1));
            mt0 = fmaxf(mt0, __shfl_xor_sync(0xffffffffu, mt0, 2));
            mt8 = fmaxf(mt8, __shfl_xor_sync(0xffffffffu, mt8, 1));
            mt8 = fmaxf(mt8, __shfl_xor_sync(0xffffffffu, mt8, 2));
            float nm0 = fmaxf(m0, mt0), nm8 = fmaxf(m8, mt8);
            float al0 = __expf(m0 - nm0), al8 = __expf(m8 - nm8);
            m0 = nm0; m8 = nm8;
            float ps0 = 0.f, ps8 = 0.f;
#pragma unroll
            for (int n = 0; n < 8; n++) {
                p[n][0] = __expf(p[n][0] - nm0);
                p[n][1] = __expf(p[n][1] - nm0);
                p[n][2] = __expf(p[n][2] - nm8);
                p[n][3] = __expf(p[n][3] - nm8);
                ps0 += p[n][0] + p[n][1];
                ps8 += p[n][2] + p[n][3];
            }
            ps0 += __shfl_xor_sync(0xffffffffu, ps0, 1);
            ps0 += __shfl_xor_sync(0xffffffffu, ps0, 2);
            ps8 += __shfl_xor_sync(0xffffffffu, ps8, 1);
            ps8 += __shfl_xor_sync(0xffffffffu, ps8, 2);
            l0 = l0 * al0 + ps0;
            l8 = l8 * al8 + ps8;
#pragma unroll
            for (int n = 0; n < 8; n++) {
                o_[n][0] *= al0; o_[n][1] *= al0;
                o_[n][2] *= al8; o_[n][3] *= al8;
            }
        }
        __syncthreads();             // all warps done reading Ks before Ps write

        if (active) {
            // ---- write P (tf32) to Ps (own rows only) ----
#pragma unroll
            for (int n = 0; n < 8; n++) {
                uint2 lo = make_uint2(f2tf32(p[n][0]), f2tf32(p[n][1]));
                uint2 hi = make_uint2(f2tf32(p[n][2]), f2tf32(p[n][3]));
                *(uint2*)&KP[rloc * 68 + n * 8 + 2 * tig] = lo;
                *(uint2*)&KP[(rloc + 8) * 68 + n * 8 + 2 * tig] = hi;
            }
            // ---- O += P V  (reads only this warp's Ps rows; no sync needed) ----
#pragma unroll
            for (int ks = 0; ks < 8; ks++) {
                int kb = ks * 8;
                uint32_t a[4];
                a[0] = KP[rloc * 68 + kb + tig];
                a[1] = KP[(rloc + 8) * 68 + kb + tig];
                a[2] = KP[rloc * 68 + kb + tig + 4];
                a[3] = KP[(rloc + 8) * 68 + kb + tig + 4];
#pragma unroll
                for (int n = 0; n < 8; n++) {
                    uint32_t bf[2];
                    bf[0] = Vs[(kb + tig) * 72 + n * 8 + g];
                    bf[1] = Vs[(kb + tig + 4) * 72 + n * 8 + g];
                    mma_tf32(o_[n], a, bf);
                }
            }
        }
    }

    // ---- finalize + write O ----
    float inv0 = 1.0f / l0, inv8 = 1.0f / l8;
    size_t base0 = (size_t)(b * SS + q0 + rloc) * DD + h * HSZ;
    size_t base8 = base0 + 8 * DD;
#pragma unroll
    for (int n = 0; n < 8; n++) {
        int col = n * 8 + 2 * tig;
        *(float2*)&O[base0 + col] = make_float2(o_[n][0] * inv0, o_[n][1] * inv0);
        *(float2*)&O[base8 + col] = make_float2(o_[n][2] * inv8, o_[n][3] * inv8);
    }
}

// ==================== host launcher ========================================
extern "C" void kernel_launch(void* const* d_in, const int* in_sizes, int n_in,
                              void* d_out, int out_size)
{
    const float* x      = (const float*)d_in[0];
    const float* wq     = (const float*)d_in[1];
    const float* wk     = (const float*)d_in[2];
    const float* wv     = (const float*)d_in[3];
    const float* proj_w = (const float*)d_in[4];
    const float* proj_b = (const float*)d_in[5];
    const float* ff1_w  = (const float*)d_in[6];
    const float* ff1_b  = (const float*)d_in[7];
    const float* ff2_w  = (const float*)d_in[8];
    const float* ff2_b  = (const float*)d_in[9];
    const float* ln1_g  = (const float*)d_in[10];
    const float* ln1_b  = (const float*)d_in[11];
    const float* ln2_g  = (const float*)d_in[12];
    const float* ln2_b  = (const float*)d_in[13];
    float* out = (float*)d_out;

    static float *h = nullptr, *qkv, *wpack, *o, *ffh;
    if (!h) {
        cudaGetSymbolAddress((void**)&h,     g_h);
        cudaGetSymbolAddress((void**)&qkv,   g_qkv);
        cudaGetSymbolAddress((void**)&wpack, g_wqkv);
        cudaGetSymbolAddress((void**)&o,     g_o);
        cudaGetSymbolAddress((void**)&ffh,   g_ffh);
        cudaFuncSetAttribute(attn_tc_kernel,
                             cudaFuncAttributeMaxDynamicSharedMemorySize,
                             ATT_SMEM_BYTES);
    }

    // 1. pack qkv weights
    repack_kernel<<<(DD * QKV_N + 255) / 256, 256>>>(wq, wk, wv, wpack);
    // 2. h = LN1(x)
    ln_kernel<<<NROWS, 256>>>(x, ln1_g, ln1_b, h);
    // 3. qkv = h @ Wqkv
    tf32gemm_kernel<<<dim3(QKV_N / 128, NROWS / 128), 256>>>(
        NROWS, QKV_N, DD, h, wpack, nullptr, nullptr, qkv, 0);
    // 4. flash attention -> o (head-concat)
    attn_tc_kernel<<<dim3(SS / 128, HH, BB), 256, ATT_SMEM_BYTES>>>(qkv, o);
    // 5. out = x + o @ proj_w + proj_b
    tf32gemm_kernel<<<dim3(DD / 128, NROWS / 128), 256>>>(
        NROWS, DD, DD, o, proj_w, proj_b, x, out, 1 | 2);
    // 6. h = LN2(out)
    ln_kernel<<<NROWS, 256>>>(out, ln2_g, ln2_b, h);
    // 7. ffh = relu(h @ ff1_w + ff1_b)
    tf32gemm_kernel<<<dim3(DFF / 128, NROWS / 128), 256>>>(
        NROWS, DFF, DD, h, ff1_w, ff1_b, nullptr, ffh, 1 | 4);
    // 8. out += ffh @ ff2_w + ff2_b
    tf32gemm_kernel<<<dim3(DD / 128, NROWS / 128), 256>>>(
        NROWS, DD, DFF, ffh, ff2_w, ff2_b, out, out, 1 | 2);
}

// round 7
// speedup vs baseline: 3.4176x; 1.2196x over previous
#include <cuda_runtime.h>
#include <cuda_bf16.h>
#include <math.h>
#include <stdint.h>

// ---------------- problem constants ----------------
#define BB 4
#define SS 2048
#define DD 1024
#define HH 16
#define HSZ 64
#define DFF 4096
#define NROWS (BB * SS)          // 8192
#define QKV_N (3 * DD)           // 3072

// ---------------- scratch (static device globals; no cudaMalloc allowed) ----
__device__ float g_h[NROWS * DD];        // LN output (tf32-rounded)
__device__ float g_qkv[NROWS * QKV_N];   // Q|K|V, head-concat (tf32-rounded)
__device__ float g_wqkv[DD * QKV_N];     // packed qkv weights (tf32-rounded)
__device__ float g_o[NROWS * DD];        // attention output (tf32-rounded)
__device__ float g_ffh[NROWS * DFF];     // FFN hidden (tf32-rounded)
__device__ float g_wproj[DD * DD];       // tf32 copy of proj_w
__device__ float g_wff1[DD * DFF];       // tf32 copy of ff1_w
__device__ float g_wff2[DFF * DD];       // tf32 copy of ff2_w

// ==================== helpers ==============================================
__device__ __forceinline__ uint32_t f2tf32(float x) {
    uint32_t t;
    asm("cvt.rna.tf32.f32 %0, %1;" : "=r"(t) : "f"(x));
    return t;
}
__device__ __forceinline__ float rtf(float x) {
    return __uint_as_float(f2tf32(x));
}
__device__ __forceinline__ void mma_tf32(float* c, const uint32_t* a,
                                         const uint32_t* b) {
    asm volatile(
        "mma.sync.aligned.m16n8k8.row.col.f32.tf32.tf32.f32 "
        "{%0,%1,%2,%3}, {%4,%5,%6,%7}, {%8,%9}, {%0,%1,%2,%3};\n"
        : "+f"(c[0]), "+f"(c[1]), "+f"(c[2]), "+f"(c[3])
        : "r"(a[0]), "r"(a[1]), "r"(a[2]), "r"(a[3]),
          "r"(b[0]), "r"(b[1]));
}
__device__ __forceinline__ uint32_t s2u(const void* p) {
    return (uint32_t)__cvta_generic_to_shared(p);
}
__device__ __forceinline__ void cpasync16(uint32_t dst, const void* src) {
    asm volatile("cp.async.ca.shared.global [%0], [%1], 16;\n"
                 :: "r"(dst), "l"(src));
}

// ==================== tf32 round-copy (weights) =============================
__global__ void roundcopy_kernel(const float* __restrict__ src,
                                 float* __restrict__ dst, int n4)
{
    int i = blockIdx.x * 256 + threadIdx.x;
    if (i >= n4) return;
    float4 v = ((const float4*)src)[i];
    v.x = rtf(v.x); v.y = rtf(v.y); v.z = rtf(v.z); v.w = rtf(v.w);
    ((float4*)dst)[i] = v;
}

// ==================== weight repack: wq/wk/wv [H,D,HS] -> W[d][n], tf32 =====
__global__ void repack_kernel(const float* __restrict__ wq,
                              const float* __restrict__ wk,
                              const float* __restrict__ wv,
                              float* __restrict__ W)
{
    int idx = blockIdx.x * 256 + threadIdx.x;
    if (idx >= DD * QKV_N) return;
    int d = idx / QKV_N;
    int n = idx % QKV_N;
    int sel = n >> 10;
    int nn  = n & 1023;
    int hh  = nn >> 6;
    int e   = nn & 63;
    const float* src = (sel == 0) ? wq : (sel == 1) ? wk : wv;
    W[idx] = rtf(src[((size_t)hh * DD + d) * HSZ + e]);
}

// ==================== LayerNorm (tf32-rounded output) =======================
__global__ void ln_kernel(const float* __restrict__ in,
                          const float* __restrict__ gg,
                          const float* __restrict__ bb,
                          float* __restrict__ out)
{
    int row = blockIdx.x;
    const float* x = in + (size_t)row * DD;
    float v[4];
    float s = 0.f, s2 = 0.f;
#pragma unroll
    for (int k = 0; k < 4; k++) {
        v[k] = x[threadIdx.x + k * 256];
        s  += v[k];
        s2 += v[k] * v[k];
    }
#pragma unroll
    for (int off = 16; off; off >>= 1) {
        s  += __shfl_xor_sync(0xffffffffu, s,  off);
        s2 += __shfl_xor_sync(0xffffffffu, s2, off);
    }
    __shared__ float red[2][8];
    int wid = threadIdx.x >> 5, lane = threadIdx.x & 31;
    if (lane == 0) { red[0][wid] = s; red[1][wid] = s2; }
    __syncthreads();
    float S = 0.f, S2 = 0.f;
#pragma unroll
    for (int w = 0; w < 8; w++) { S += red[0][w]; S2 += red[1][w]; }
    float mean = S * (1.0f / DD);
    float var  = S2 * (1.0f / DD) - mean * mean;
    float rstd = rsqrtf(var + 1e-5f);
    float* o = out + (size_t)row * DD;
#pragma unroll
    for (int k = 0; k < 4; k++) {
        int c = threadIdx.x + k * 256;
        o[c] = rtf((v[k] - mean) * rstd * gg[c] + bb[c]);
    }
}

// ==================== TF32 GEMM, cp.async double-buffered ===================
// Inputs A,B MUST be tf32-representable fp32 (pre-rounded).
// flags: 1 = +bias[col], 2 = +res, 4 = relu, 8 = round output to tf32
#define AS_WORDS (128 * 36)
#define BS_WORDS (32 * 136)
#define GEMM_SMEM_BYTES ((AS_WORDS + BS_WORDS) * 2 * 4)

__global__ __launch_bounds__(256, 2)
void tf32gemm_kernel(int M, int N, int K,
                     const float* __restrict__ A,
                     const float* __restrict__ Bm,
                     const float* __restrict__ bias,
                     const float* __restrict__ res,
                     float* __restrict__ C,
                     int flags)
{
    extern __shared__ __align__(16) uint32_t dsm[];
    uint32_t* AsB = dsm;                       // 2 x [128][36]
    uint32_t* BsB = dsm + 2 * AS_WORDS;        // 2 x [32][136]

    int tid  = threadIdx.x;
    int lane = tid & 31;
    int warp = tid >> 5;
    int g    = lane >> 2;
    int tig  = lane & 3;
    int warp_m = warp & 1;
    int warp_n = warp >> 1;
    int m0 = blockIdx.y * 128;
    int n0 = blockIdx.x * 128;

    float acc[4][4][4];
#pragma unroll
    for (int i = 0; i < 4; i++)
#pragma unroll
        for (int j = 0; j < 4; j++)
#pragma unroll
            for (int c = 0; c < 4; c++) acc[i][j][c] = 0.f;

    auto load_tiles = [&](int k0, int buf) {
        uint32_t* as = AsB + buf * AS_WORDS;
        uint32_t* bs = BsB + buf * BS_WORDS;
#pragma unroll
        for (int q = 0; q < 4; q++) {           // A tile: 128x32 = 1024 chunks
            int ch = q * 256 + tid;
            int r = ch >> 3, cc = ch & 7;
            cpasync16(s2u(as + r * 36 + cc * 4),
                      A + (size_t)(m0 + r) * K + k0 + cc * 4);
        }
#pragma unroll
        for (int q = 0; q < 4; q++) {           // B tile: 32x128 = 1024 chunks
            int ch = q * 256 + tid;
            int kr = ch >> 5, cc = ch & 31;
            cpasync16(s2u(bs + kr * 136 + cc * 4),
                      Bm + (size_t)(k0 + kr) * N + n0 + cc * 4);
        }
    };

    load_tiles(0, 0);
    asm volatile("cp.async.commit_group;\n");

    int nk = K / 32;
    for (int kt = 0; kt < nk; kt++) {
        int cur = kt & 1;
        if (kt + 1 < nk) {
            load_tiles((kt + 1) * 32, cur ^ 1);
            asm volatile("cp.async.commit_group;\n");
            asm volatile("cp.async.wait_group 1;\n");
        } else {
            asm volatile("cp.async.wait_group 0;\n");
        }
        __syncthreads();

        const uint32_t* As = AsB + cur * AS_WORDS;
        const uint32_t* Bs = BsB + cur * BS_WORDS;
#pragma unroll
        for (int ks = 0; ks < 4; ks++) {
            int kb = ks * 8;
            uint32_t afr[4][4], bfr[4][2];
#pragma unroll
            for (int i = 0; i < 4; i++) {
                int r = warp_m * 64 + i * 16 + g;
                afr[i][0] = As[r * 36 + kb + tig];
                afr[i][1] = As[(r + 8) * 36 + kb + tig];
                afr[i][2] = As[r * 36 + kb + tig + 4];
                afr[i][3] = As[(r + 8) * 36 + kb + tig + 4];
            }
#pragma unroll
            for (int j = 0; j < 4; j++) {
                int n = warp_n * 32 + j * 8 + g;
                bfr[j][0] = Bs[(kb + tig) * 136 + n];
                bfr[j][1] = Bs[(kb + tig + 4) * 136 + n];
            }
#pragma unroll
            for (int i = 0; i < 4; i++)
#pragma unroll
                for (int j = 0; j < 4; j++)
                    mma_tf32(acc[i][j], afr[i], bfr[j]);
        }
        __syncthreads();
    }

    // ---- epilogue ----
#pragma unroll
    for (int j = 0; j < 4; j++) {
        int col = n0 + warp_n * 32 + j * 8 + 2 * tig;
        float b0 = 0.f, b1 = 0.f;
        if (flags & 1) { b0 = bias[col]; b1 = bias[col + 1]; }
#pragma unroll
        for (int i = 0; i < 4; i++) {
            int r = m0 + warp_m * 64 + i * 16 + g;
#pragma unroll
            for (int half = 0; half < 2; half++) {
                int row = r + half * 8;
                size_t base = (size_t)row * N + col;
                float v0 = acc[i][j][half * 2 + 0] + b0;
                float v1 = acc[i][j][half * 2 + 1] + b1;
                if (flags & 2) {
                    float2 rr = *(const float2*)(res + base);
                    v0 += rr.x; v1 += rr.y;
                }
                if (flags & 4) { v0 = fmaxf(v0, 0.f); v1 = fmaxf(v1, 0.f); }
                if (flags & 8) { v0 = rtf(v0); v1 = rtf(v1); }
                *(float2*)(C + base) = make_float2(v0, v1);
            }
        }
    }
}

// ==================== TF32 tensor-core flash attention ======================
// Inputs (qkv) pre-rounded to tf32: tile loads are straight bit copies.
#define ATT_SMEM_BYTES ((128*68 + 128*68 + 64*72) * 4)

__global__ __launch_bounds__(256, 2)
void attn_tc_kernel(const float* __restrict__ qkv, float* __restrict__ O)
{
    extern __shared__ uint32_t sm[];
    uint32_t* Qs = sm;                   // [128][68]
    uint32_t* KP = sm + 128 * 68;        // Ks[64][68] / Ps[128][68]
    uint32_t* Vs = sm + 2 * 128 * 68;    // [64][72]

    int b  = blockIdx.z;
    int h  = blockIdx.y;
    int q0 = blockIdx.x * 128;
    int tid  = threadIdx.x;
    int lane = tid & 31, warp = tid >> 5;
    int g    = lane >> 2, tig = lane & 3;

    // ---- load Q tile (128x64) ----
    {
        int r  = tid >> 1;
        int c0 = (tid & 1) * 32;
        const float* src = qkv + (size_t)(b * SS + q0 + r) * QKV_N + h * HSZ + c0;
#pragma unroll
        for (int q = 0; q < 8; q++)
            *(uint4*)&Qs[r * 68 + c0 + q * 4] = *(const uint4*)(src + q * 4);
    }

    float o_[8][4];
#pragma unroll
    for (int n = 0; n < 8; n++)
#pragma unroll
        for (int c = 0; c < 4; c++) o_[n][c] = 0.f;
    float m0 = -1e30f, m8 = -1e30f, l0 = 0.f, l8 = 0.f;

    int Rw   = q0 + warp * 16;
    int row0 = Rw + g;
    int rmax = Rw + 15;
    int rloc = warp * 16 + g;

    int ntile = 2 * blockIdx.x + 2;
    for (int jt = 0; jt < ntile; jt++) {
        int j0 = jt * 64;
        __syncthreads();
        // ---- load K,V tiles (64x64 each) ----
        {
            int t  = tid >> 2;
            int c0 = (tid & 3) * 16;
            const float* kp = qkv + (size_t)(b * SS + j0 + t) * QKV_N + DD + h * HSZ + c0;
#pragma unroll
            for (int q = 0; q < 4; q++) {
                *(uint4*)&KP[t * 68 + c0 + q * 4] = *(const uint4*)(kp + q * 4);
                *(uint4*)&Vs[t * 72 + c0 + q * 4] = *(const uint4*)(kp + DD + q * 4);
            }
        }
        __syncthreads();

        bool active = (j0 <= rmax);
        float p[8][4];
        if (active) {
#pragma unroll
            for (int n = 0; n < 8; n++)
#pragma unroll
                for (int c = 0; c < 4; c++) p[n][c] = 0.f;
#pragma unroll
            for (int ks = 0; ks < 8; ks++) {
                int kb = ks * 8;
                uint32_t a[4];
                a[0] = Qs[rloc * 68 + kb + tig];
                a[1] = Qs[(rloc + 8) * 68 + kb + tig];
                a[2] = Qs[rloc * 68 + kb + tig + 4];
                a[3] = Qs[(rloc + 8) * 68 + kb + tig + 4];
#pragma unroll
                for (int n = 0; n < 8; n++) {
                    uint32_t bf[2];
                    bf[0] = KP[(n * 8 + g) * 68 + kb + tig];
                    bf[1] = KP[(n * 8 + g) * 68 + kb + tig + 4];
                    mma_tf32(p[n], a, bf);
                }
            }
            bool needmask = (j0 + 63 > Rw);
            float mt0 = -1e30f, mt8 = -1e30f;
#pragma unroll
            for (int n = 0; n < 8; n++) {
#pragma unroll
                for (int c = 0; c < 4; c++) {
                    float v = p[n][c] * 0.125f;
                    if (needmask) {
                        int col = j0 + n * 8 + 2 * tig + (c & 1);
                        int row = row0 + (c >> 1) * 8;
                        if (col > row) v = -1e30f;
                    }
                    p[n][c] = v;
                    if (c < 2) mt0 = fmaxf(mt0, v); else mt8 = fmaxf(mt8, v);
                }
            }
            mt0 = fmaxf(mt0, __shfl_xor_sync(0xffffffffu, mt0, 1));
            mt0 = fmaxf(mt0, __shfl_xor_sync(0xffffffffu, mt0, 2));
            mt8 = fmaxf(mt8, __shfl_xor_sync(0xffffffffu, mt8, 1));
            mt8 = fmaxf(mt8, __shfl_xor_sync(0xffffffffu, mt8, 2));
            float nm0 = fmaxf(m0, mt0), nm8 = fmaxf(m8, mt8);
            float al0 = __expf(m0 - nm0), al8 = __expf(m8 - nm8);
            m0 = nm0; m8 = nm8;
            float ps0 = 0.f, ps8 = 0.f;
#pragma unroll
            for (int n = 0; n < 8; n++) {
                p[n][0] = __expf(p[n][0] - nm0);
                p[n][1] = __expf(p[n][1] - nm0);
                p[n][2] = __expf(p[n][2] - nm8);
                p[n][3] = __expf(p[n][3] - nm8);
                ps0 += p[n][0] + p[n][1];
                ps8 += p[n][2] + p[n][3];
            }
            ps0 += __shfl_xor_sync(0xffffffffu, ps0, 1);
            ps0 += __shfl_xor_sync(0xffffffffu, ps0, 2);
            ps8 += __shfl_xor_sync(0xffffffffu, ps8, 1);
            ps8 += __shfl_xor_sync(0xffffffffu, ps8, 2);
            l0 = l0 * al0 + ps0;
            l8 = l8 * al8 + ps8;
#pragma unroll
            for (int n = 0; n < 8; n++) {
                o_[n][0] *= al0; o_[n][1] *= al0;
                o_[n][2] *= al8; o_[n][3] *= al8;
            }
        }
        __syncthreads();

        if (active) {
#pragma unroll
            for (int n = 0; n < 8; n++) {
                uint2 lo = make_uint2(f2tf32(p[n][0]), f2tf32(p[n][1]));
                uint2 hi = make_uint2(f2tf32(p[n][2]), f2tf32(p[n][3]));
                *(uint2*)&KP[rloc * 68 + n * 8 + 2 * tig] = lo;
                *(uint2*)&KP[(rloc + 8) * 68 + n * 8 + 2 * tig] = hi;
            }
#pragma unroll
            for (int ks = 0; ks < 8; ks++) {
                int kb = ks * 8;
                uint32_t a[4];
                a[0] = KP[rloc * 68 + kb + tig];
                a[1] = KP[(rloc + 8) * 68 + kb + tig];
                a[2] = KP[rloc * 68 + kb + tig + 4];
                a[3] = KP[(rloc + 8) * 68 + kb + tig + 4];
#pragma unroll
                for (int n = 0; n < 8; n++) {
                    uint32_t bf[2];
                    bf[0] = Vs[(kb + tig) * 72 + n * 8 + g];
                    bf[1] = Vs[(kb + tig + 4) * 72 + n * 8 + g];
                    mma_tf32(o_[n], a, bf);
                }
            }
        }
    }

    // ---- finalize + write O (tf32-rounded: feeds proj GEMM A operand) ----
    float inv0 = 1.0f / l0, inv8 = 1.0f / l8;
    size_t base0 = (size_t)(b * SS + q0 + rloc) * DD + h * HSZ;
    size_t base8 = base0 + 8 * DD;
#pragma unroll
    for (int n = 0; n < 8; n++) {
        int col = n * 8 + 2 * tig;
        *(float2*)&O[base0 + col] =
            make_float2(rtf(o_[n][0] * inv0), rtf(o_[n][1] * inv0));
        *(float2*)&O[base8 + col] =
            make_float2(rtf(o_[n][2] * inv8), rtf(o_[n][3] * inv8));
    }
}

// ==================== host launcher ========================================
extern "C" void kernel_launch(void* const* d_in, const int* in_sizes, int n_in,
                              void* d_out, int out_size)
{
    const float* x      = (const float*)d_in[0];
    const float* wq     = (const float*)d_in[1];
    const float* wk     = (const float*)d_in[2];
    const float* wv     = (const float*)d_in[3];
    const float* proj_w = (const float*)d_in[4];
    const float* proj_b = (const float*)d_in[5];
    const float* ff1_w  = (const float*)d_in[6];
    const float* ff1_b  = (const float*)d_in[7];
    const float* ff2_w  = (const float*)d_in[8];
    const float* ff2_b  = (const float*)d_in[9];
    const float* ln1_g  = (const float*)d_in[10];
    const float* ln1_b  = (const float*)d_in[11];
    const float* ln2_g  = (const float*)d_in[12];
    const float* ln2_b  = (const float*)d_in[13];
    float* out = (float*)d_out;

    static float *h = nullptr, *qkv, *wpack, *o, *ffh, *wproj, *wff1, *wff2;
    if (!h) {
        cudaGetSymbolAddress((void**)&h,     g_h);
        cudaGetSymbolAddress((void**)&qkv,   g_qkv);
        cudaGetSymbolAddress((void**)&wpack, g_wqkv);
        cudaGetSymbolAddress((void**)&o,     g_o);
        cudaGetSymbolAddress((void**)&ffh,   g_ffh);
        cudaGetSymbolAddress((void**)&wproj, g_wproj);
        cudaGetSymbolAddress((void**)&wff1,  g_wff1);
        cudaGetSymbolAddress((void**)&wff2,  g_wff2);
        cudaFuncSetAttribute(attn_tc_kernel,
                             cudaFuncAttributeMaxDynamicSharedMemorySize,
                             ATT_SMEM_BYTES);
        cudaFuncSetAttribute(tf32gemm_kernel,
                             cudaFuncAttributeMaxDynamicSharedMemorySize,
                             GEMM_SMEM_BYTES);
    }

    // 0. tf32-round weight copies
    repack_kernel<<<(DD * QKV_N + 255) / 256, 256>>>(wq, wk, wv, wpack);
    roundcopy_kernel<<<(DD * DD / 4 + 255) / 256, 256>>>(proj_w, wproj, DD * DD / 4);
    roundcopy_kernel<<<(DD * DFF / 4 + 255) / 256, 256>>>(ff1_w, wff1, DD * DFF / 4);
    roundcopy_kernel<<<(DFF * DD / 4 + 255) / 256, 256>>>(ff2_w, wff2, DFF * DD / 4);
    // 1. h = LN1(x)  (tf32-rounded)
    ln_kernel<<<NROWS, 256>>>(x, ln1_g, ln1_b, h);
    // 2. qkv = h @ Wqkv  (round output -> attention inputs)
    tf32gemm_kernel<<<dim3(QKV_N / 128, NROWS / 128), 256, GEMM_SMEM_BYTES>>>(
        NROWS, QKV_N, DD, h, wpack, nullptr, nullptr, qkv, 8);
    // 3. flash attention -> o (tf32-rounded)
    attn_tc_kernel<<<dim3(SS / 128, HH, BB), 256, ATT_SMEM_BYTES>>>(qkv, o);
    // 4. out = x + o @ proj_w + proj_b
    tf32gemm_kernel<<<dim3(DD / 128, NROWS / 128), 256, GEMM_SMEM_BYTES>>>(
        NROWS, DD, DD, o, wproj, proj_b, x, out, 1 | 2);
    // 5. h = LN2(out)  (tf32-rounded)
    ln_kernel<<<NROWS, 256>>>(out, ln2_g, ln2_b, h);
    // 6. ffh = relu(h @ ff1_w + ff1_b)  (round output)
    tf32gemm_kernel<<<dim3(DFF / 128, NROWS / 128), 256, GEMM_SMEM_BYTES>>>(
        NROWS, DFF, DD, h, wff1, ff1_b, nullptr, ffh, 1 | 4 | 8);
    // 7. out += ffh @ ff2_w + ff2_b
    tf32gemm_kernel<<<dim3(DD / 128, NROWS / 128), 256, GEMM_SMEM_BYTES>>>(
        NROWS, DD, DFF, ffh, wff2, ff2_b, out, out, 1 | 2);
}